// round 2
// baseline (speedup 1.0000x reference)
#include <cuda_runtime.h>
#include <cuda_bf16.h>
#include <math.h>

#define B_   2
#define S_   2048
#define E_   1024
#define NH_  16
#define NKV_ 4
#define HD_  64
#define GATE_CH_ 12
#define TOKENS (B_ * S_)   // 4096

// ---------------------------------------------------------------------------
// Scratch (device globals: no allocation allowed)
// ---------------------------------------------------------------------------
__device__ float g_q[TOKENS * NH_ * HD_];    // (b,s,h,d)   16 MB
__device__ float g_k[TOKENS * NKV_ * HD_];   // (b,s,kv,d)   4 MB
__device__ float g_v[TOKENS * NKV_ * HD_];   // (b,s,kv,d)   4 MB
__device__ float g_y[TOKENS * NH_ * HD_];    // (b,s,h*64+d) 16 MB

// ---------------------------------------------------------------------------
// GEMM:  C[M,N] = A[M,K] @ W[N,K]^T     (all row-major, fp32)
// 64x64 tile, BK=16, 256 threads, 4x4 register tile per thread.
// M % 64 == 0, N % 64 == 0, K % 16 == 0 guaranteed by the shapes here.
// ---------------------------------------------------------------------------
#define BM 64
#define BN 64
#define BK 16

__global__ __launch_bounds__(256)
void gemm_abt_kernel(const float* __restrict__ A,
                     const float* __restrict__ W,
                     float* __restrict__ C,
                     int M, int N, int K)
{
    __shared__ float As[BK][BM];
    __shared__ float Ws[BK][BN];

    const int bm = blockIdx.y * BM;
    const int bn = blockIdx.x * BN;
    const int tid = threadIdx.x;

    const int lr  = tid >> 2;          // 0..63  row within tile for loading
    const int lc  = (tid & 3) * 4;     // 0,4,8,12 k-offset (float4)

    const int ty = tid >> 4;           // 0..15
    const int tx = tid & 15;           // 0..15

    float acc[4][4];
#pragma unroll
    for (int i = 0; i < 4; i++)
#pragma unroll
        for (int j = 0; j < 4; j++) acc[i][j] = 0.f;

    const float* Arow = A + (size_t)(bm + lr) * K + lc;
    const float* Wrow = W + (size_t)(bn + lr) * K + lc;

    for (int k0 = 0; k0 < K; k0 += BK) {
        float4 a4 = *(const float4*)(Arow + k0);
        float4 w4 = *(const float4*)(Wrow + k0);
        As[lc + 0][lr] = a4.x; As[lc + 1][lr] = a4.y;
        As[lc + 2][lr] = a4.z; As[lc + 3][lr] = a4.w;
        Ws[lc + 0][lr] = w4.x; Ws[lc + 1][lr] = w4.y;
        Ws[lc + 2][lr] = w4.z; Ws[lc + 3][lr] = w4.w;
        __syncthreads();

#pragma unroll
        for (int k = 0; k < BK; k++) {
            float4 ra = *(const float4*)&As[k][ty * 4];
            float4 rw = *(const float4*)&Ws[k][tx * 4];
            float a0 = ra.x, a1 = ra.y, a2 = ra.z, a3 = ra.w;
            float w0 = rw.x, w1 = rw.y, w2 = rw.z, w3 = rw.w;
            acc[0][0] += a0 * w0; acc[0][1] += a0 * w1; acc[0][2] += a0 * w2; acc[0][3] += a0 * w3;
            acc[1][0] += a1 * w0; acc[1][1] += a1 * w1; acc[1][2] += a1 * w2; acc[1][3] += a1 * w3;
            acc[2][0] += a2 * w0; acc[2][1] += a2 * w1; acc[2][2] += a2 * w2; acc[2][3] += a2 * w3;
            acc[3][0] += a3 * w0; acc[3][1] += a3 * w1; acc[3][2] += a3 * w2; acc[3][3] += a3 * w3;
        }
        __syncthreads();
    }

#pragma unroll
    for (int i = 0; i < 4; i++) {
        float* crow = C + (size_t)(bm + ty * 4 + i) * N + bn + tx * 4;
        float4 out = make_float4(acc[i][0], acc[i][1], acc[i][2], acc[i][3]);
        *(float4*)crow = out;
    }
}

// ---------------------------------------------------------------------------
// Elementwise: gate+ve on V, rope+rmsnorm(*1.2) on Q and K.
// One block per token, 256 threads (8 warps).
// ---------------------------------------------------------------------------
__global__ __launch_bounds__(256)
void ew_kernel(const float* __restrict__ x,
               const float* __restrict__ ve,
               const float* __restrict__ cosb,
               const float* __restrict__ sinb,
               const float* __restrict__ Wgate)
{
    const int token = blockIdx.x;            // b*S + s
    const int s = token % S_;
    const int tid = threadIdx.x;

    __shared__ float gate_s[NKV_];
    __shared__ float cs[32], sn[32];

    if (tid < 32) {
        cs[tid] = cosb[s * 32 + tid];
        sn[tid] = sinb[s * 32 + tid];
    }
    if (tid >= 32 && tid < 32 + NKV_) {
        int kv = tid - 32;
        float acc = 0.f;
#pragma unroll
        for (int c = 0; c < GATE_CH_; c++)
            acc += x[(size_t)token * E_ + c] * Wgate[kv * GATE_CH_ + c];
        gate_s[kv] = 3.f / (1.f + expf(-acc));
    }
    __syncthreads();

    // v += gate * ve   (256 values per token)
    {
        int kv = tid >> 6;                    // tid/64
        float g = gate_s[kv];
        size_t idx = (size_t)token * (NKV_ * HD_) + tid;
        g_v[idx] += g * ve[idx];
    }

    // rope + rmsnorm on q (16 heads) and k (4 heads): 20 head-units, 8 warps
    const int warp = tid >> 5, lane = tid & 31;
    const float c = cs[lane], si = sn[lane];

    for (int hh = warp; hh < NH_ + NKV_; hh += 8) {
        float* base;
        if (hh < NH_) base = g_q + (size_t)token * (NH_ * HD_) + hh * HD_;
        else          base = g_k + (size_t)token * (NKV_ * HD_) + (hh - NH_) * HD_;

        float x1 = base[lane];
        float x2 = base[lane + 32];
        float o1 =  x1 * c  + x2 * si;
        float o2 = -x1 * si + x2 * c;

        float ss = o1 * o1 + o2 * o2;
#pragma unroll
        for (int o = 16; o > 0; o >>= 1)
            ss += __shfl_xor_sync(0xffffffffu, ss, o);
        float r = rsqrtf(ss * (1.f / HD_) + 1.1920929e-7f) * 1.2f;
        base[lane]      = o1 * r;
        base[lane + 32] = o2 * r;
    }
}

// ---------------------------------------------------------------------------
// Flash attention, fp32. 64 query rows per block, 1 row per thread.
// grid = (S/64 q-tiles, B*NH).  Causal, GQA (kv head = h/4), scale 1/8.
// ---------------------------------------------------------------------------
__global__ __launch_bounds__(64)
void attn_kernel()
{
    const int qt = blockIdx.x;               // 0..31
    const int bh = blockIdx.y;               // 0..31
    const int b = bh / NH_, h = bh % NH_;
    const int kvh = h / (NH_ / NKV_);

    __shared__ float Ks[64 * 64];
    __shared__ float Vs[64 * 64];
    __shared__ float Ss[64 * 64];            // Ss[j*64 + tid]

    const int tid = threadIdx.x;             // 0..63
    const int qrow = qt * 64 + tid;

    float qreg[64];
    {
        const float4* qp = (const float4*)(g_q + (((size_t)(b * S_ + qrow)) * NH_ + h) * HD_);
#pragma unroll
        for (int i = 0; i < 16; i++) {
            float4 t = qp[i];
            qreg[4 * i + 0] = t.x; qreg[4 * i + 1] = t.y;
            qreg[4 * i + 2] = t.z; qreg[4 * i + 3] = t.w;
        }
    }

    float m = -INFINITY, l = 0.f;
    float acc[64];
#pragma unroll
    for (int d = 0; d < 64; d++) acc[d] = 0.f;

    for (int t = 0; t <= qt; t++) {
        __syncthreads();
        // cooperative K/V tile load (coalesced float4 rows)
        for (int idx = tid; idx < 64 * 16; idx += 64) {
            int r = idx >> 4, c4 = idx & 15;
            size_t gbase = (((size_t)(b * S_ + t * 64 + r)) * NKV_ + kvh) * HD_;
            ((float4*)Ks)[r * 16 + c4] = ((const float4*)(g_k + gbase))[c4];
            ((float4*)Vs)[r * 16 + c4] = ((const float4*)(g_v + gbase))[c4];
        }
        __syncthreads();

        const int kmax = (t == qt) ? (tid + 1) : 64;   // causal valid-key count

        float tmax = -INFINITY;
        for (int j = 0; j < 64; j++) {
            float sdot = 0.f;
            const float4* kr = (const float4*)(Ks + j * 64);
#pragma unroll
            for (int i = 0; i < 16; i++) {
                float4 k4 = kr[i];
                sdot += qreg[4 * i + 0] * k4.x + qreg[4 * i + 1] * k4.y
                      + qreg[4 * i + 2] * k4.z + qreg[4 * i + 3] * k4.w;
            }
            sdot *= 0.125f;                              // 1/sqrt(64)
            if (j >= kmax) sdot = -INFINITY;
            Ss[j * 64 + tid] = sdot;
            tmax = fmaxf(tmax, sdot);
        }

        float mnew = fmaxf(m, tmax);
        float corr = expf(m - mnew);
        l *= corr;
#pragma unroll
        for (int d = 0; d < 64; d++) acc[d] *= corr;

        for (int j = 0; j < 64; j++) {
            float p = expf(Ss[j * 64 + tid] - mnew);     // exp(-inf)=0 for masked
            l += p;
            const float4* vr = (const float4*)(Vs + j * 64);
#pragma unroll
            for (int i = 0; i < 16; i++) {
                float4 v4 = vr[i];
                acc[4 * i + 0] += p * v4.x; acc[4 * i + 1] += p * v4.y;
                acc[4 * i + 2] += p * v4.z; acc[4 * i + 3] += p * v4.w;
            }
        }
        m = mnew;
    }

    const float inv = 1.f / l;
    float4* yo = (float4*)(g_y + (size_t)(b * S_ + qrow) * (NH_ * HD_) + h * HD_);
#pragma unroll
    for (int i = 0; i < 16; i++)
        yo[i] = make_float4(acc[4 * i + 0] * inv, acc[4 * i + 1] * inv,
                            acc[4 * i + 2] * inv, acc[4 * i + 3] * inv);
}

// ---------------------------------------------------------------------------
// launch
// inputs: 0:x 1:ve 2:cos 3:sin 4:attn_mask 5:Wq 6:Wk 7:Wv 8:Wproj 9:Wgate
// ---------------------------------------------------------------------------
extern "C" void kernel_launch(void* const* d_in, const int* in_sizes, int n_in,
                              void* d_out, int out_size)
{
    (void)in_sizes; (void)n_in; (void)out_size;
    const float* x     = (const float*)d_in[0];
    const float* ve    = (const float*)d_in[1];
    const float* cosb  = (const float*)d_in[2];
    const float* sinb  = (const float*)d_in[3];
    const float* Wq    = (const float*)d_in[5];
    const float* Wk    = (const float*)d_in[6];
    const float* Wv    = (const float*)d_in[7];
    const float* Wproj = (const float*)d_in[8];
    const float* Wgate = (const float*)d_in[9];
    float* out = (float*)d_out;

    float *qp, *kp, *vp, *yp;
    cudaGetSymbolAddress((void**)&qp, g_q);
    cudaGetSymbolAddress((void**)&kp, g_k);
    cudaGetSymbolAddress((void**)&vp, g_v);
    cudaGetSymbolAddress((void**)&yp, g_y);

    // QKV projections
    {
        dim3 gq(NH_ * HD_ / BN, TOKENS / BM);
        gemm_abt_kernel<<<gq, 256>>>(x, Wq, qp, TOKENS, NH_ * HD_, E_);
        dim3 gk(NKV_ * HD_ / BN, TOKENS / BM);
        gemm_abt_kernel<<<gk, 256>>>(x, Wk, kp, TOKENS, NKV_ * HD_, E_);
        gemm_abt_kernel<<<gk, 256>>>(x, Wv, vp, TOKENS, NKV_ * HD_, E_);
    }

    // gate + ve, rope + rmsnorm
    ew_kernel<<<TOKENS, 256>>>(x, ve, cosb, sinb, Wgate);

    // causal GQA attention
    {
        dim3 ga(S_ / 64, B_ * NH_);
        attn_kernel<<<ga, 64>>>();
    }

    // output projection
    {
        dim3 gp(E_ / BN, TOKENS / BM);
        gemm_abt_kernel<<<gp, 256>>>(yp, Wproj, out, TOKENS, E_, E_);
    }
}

// round 3
// speedup vs baseline: 1.3069x; 1.3069x over previous
#include <cuda_runtime.h>
#include <cuda_bf16.h>
#include <math.h>
#include <stdint.h>

#define B_   2
#define S_   2048
#define E_   1024
#define NH_  16
#define NKV_ 4
#define HD_  64
#define GATE_CH_ 12
#define TOKENS (B_ * S_)   // 4096

// ---------------------------------------------------------------------------
// Scratch (device globals: no allocation allowed)
// ---------------------------------------------------------------------------
__device__ float g_q[TOKENS * NH_ * HD_];    // 16 MB
__device__ float g_k[TOKENS * NKV_ * HD_];   //  4 MB
__device__ float g_v[TOKENS * NKV_ * HD_];   //  4 MB
__device__ float g_y[TOKENS * NH_ * HD_];    // 16 MB

// split-bf16 scratch
__device__ __nv_bfloat16 g_xh[TOKENS * E_];  // 8 MB
__device__ __nv_bfloat16 g_xl[TOKENS * E_];
__device__ __nv_bfloat16 g_yh[TOKENS * E_];
__device__ __nv_bfloat16 g_yl[TOKENS * E_];
// weights: rows = 1024 (Wq) + 256 (Wk) + 256 (Wv) + 1024 (Wproj) = 2560
#define WQ_OFF 0
#define WK_OFF (1024 * E_)
#define WV_OFF (1280 * E_)
#define WP_OFF (1536 * E_)
__device__ __nv_bfloat16 g_wh[2560 * E_];    // 5 MB
__device__ __nv_bfloat16 g_wl[2560 * E_];

// ---------------------------------------------------------------------------
// split fp32 -> (hi, lo) bf16
// ---------------------------------------------------------------------------
__global__ __launch_bounds__(256)
void split_kernel(const float* __restrict__ in,
                  __nv_bfloat16* __restrict__ hi,
                  __nv_bfloat16* __restrict__ lo, int n4)
{
    int i = blockIdx.x * blockDim.x + threadIdx.x;
    if (i >= n4) return;
    float4 v = ((const float4*)in)[i];
    float vv[4] = {v.x, v.y, v.z, v.w};
    uint2 hv, lv;
    __nv_bfloat16* hp = (__nv_bfloat16*)&hv;
    __nv_bfloat16* lp = (__nv_bfloat16*)&lv;
#pragma unroll
    for (int j = 0; j < 4; j++) {
        __nv_bfloat16 h = __float2bfloat16(vv[j]);
        hp[j] = h;
        lp[j] = __float2bfloat16(vv[j] - __bfloat162float(h));
    }
    ((uint2*)hi)[i] = hv;
    ((uint2*)lo)[i] = lv;
}

// ---------------------------------------------------------------------------
// Tensor-core GEMM: C[M,N] = (Ah+Al)[M,K] @ (Wh+Wl)[N,K]^T  (3-pass split bf16)
// block tile 128x128x32, 8 warps (2x4), warp tile 64x32.
// SMEM row: 64 bf16 = 128B = [hi k0..31 | lo k0..31], XOR-8 16B-chunk swizzle.
// ---------------------------------------------------------------------------
__device__ __forceinline__ void ldsm4(uint32_t* r, uint32_t addr)
{
    asm volatile("ldmatrix.sync.aligned.m8n8.x4.shared.b16 {%0,%1,%2,%3}, [%4];"
                 : "=r"(r[0]), "=r"(r[1]), "=r"(r[2]), "=r"(r[3]) : "r"(addr));
}
__device__ __forceinline__ void mma16816(float* c, const uint32_t* a, const uint32_t* b)
{
    asm volatile(
        "mma.sync.aligned.m16n8k16.row.col.f32.bf16.bf16.f32 "
        "{%0,%1,%2,%3},{%4,%5,%6,%7},{%8,%9},{%0,%1,%2,%3};"
        : "+f"(c[0]), "+f"(c[1]), "+f"(c[2]), "+f"(c[3])
        : "r"(a[0]), "r"(a[1]), "r"(a[2]), "r"(a[3]), "r"(b[0]), "r"(b[1]));
}

__global__ __launch_bounds__(256, 1)
void gemm_split_kernel(const __nv_bfloat16* __restrict__ Ah,
                       const __nv_bfloat16* __restrict__ Al,
                       const __nv_bfloat16* __restrict__ Wh,
                       const __nv_bfloat16* __restrict__ Wl,
                       float* __restrict__ C,
                       int M, int N, int K)
{
    __shared__ __align__(16) unsigned char sA[128 * 128];
    __shared__ __align__(16) unsigned char sW[128 * 128];

    const int tid  = threadIdx.x;
    const int lane = tid & 31;
    const int warp = tid >> 5;
    const int wm = warp >> 2;          // 0..1 -> 64 rows
    const int wn = warp & 3;           // 0..3 -> 32 cols
    const int bm = blockIdx.y * 128;
    const int bn = blockIdx.x * 128;

    // loader: thread -> (row 0..31 (+32*it), chunk 0..7)
    const int lchunk = tid & 7;
    const int lrow0  = tid >> 3;
    const __nv_bfloat16* Asrc = (lchunk < 4) ? Ah : Al;
    const __nv_bfloat16* Wsrc = (lchunk < 4) ? Wh : Wl;
    const int kcoloff = (lchunk & 3) * 8;

    float acc[4][4][4];
#pragma unroll
    for (int i = 0; i < 4; i++)
#pragma unroll
        for (int j = 0; j < 4; j++)
#pragma unroll
            for (int r = 0; r < 4; r++) acc[i][j][r] = 0.f;

    const uint32_t aBase = (uint32_t)__cvta_generic_to_shared(sA);
    const uint32_t wBase = (uint32_t)__cvta_generic_to_shared(sW);

    // ldmatrix per-lane address components
    const int a_r = lane & 15;            // row within 16-row frag
    const int a_c = (lane >> 4) & 1;      // k 8-chunk
    const int b_r = ((lane >> 4) & 1) * 8 + (lane & 7);
    const int b_c = (lane >> 3) & 1;

    uint4 pa[4], pw[4];
#pragma unroll
    for (int it = 0; it < 4; it++) {
        int row = lrow0 + it * 32;
        pa[it] = *(const uint4*)(Asrc + (size_t)(bm + row) * K + kcoloff);
        pw[it] = *(const uint4*)(Wsrc + (size_t)(bn + row) * K + kcoloff);
    }

    for (int k0 = 0; k0 < K; k0 += 32) {
        __syncthreads();
#pragma unroll
        for (int it = 0; it < 4; it++) {
            int row = lrow0 + it * 32;
            *(uint4*)(sA + row * 128 + ((lchunk ^ (row & 7)) * 16)) = pa[it];
            *(uint4*)(sW + row * 128 + ((lchunk ^ (row & 7)) * 16)) = pw[it];
        }
        __syncthreads();

        if (k0 + 32 < K) {
#pragma unroll
            for (int it = 0; it < 4; it++) {
                int row = lrow0 + it * 32;
                pa[it] = *(const uint4*)(Asrc + (size_t)(bm + row) * K + k0 + 32 + kcoloff);
                pw[it] = *(const uint4*)(Wsrc + (size_t)(bn + row) * K + k0 + 32 + kcoloff);
            }
        }

#pragma unroll
        for (int kk = 0; kk < 2; kk++) {
            uint32_t ah[4][4], al[4][4], wh[4][2], wl[4][2];
#pragma unroll
            for (int mf = 0; mf < 4; mf++) {
                int R = wm * 64 + mf * 16 + a_r;
                int chi = kk * 2 + a_c;
                ldsm4(ah[mf], aBase + R * 128 + ((chi ^ (R & 7)) * 16));
                ldsm4(al[mf], aBase + R * 128 + (((chi + 4) ^ (R & 7)) * 16));
            }
#pragma unroll
            for (int np = 0; np < 2; np++) {
                int R = wn * 32 + np * 16 + b_r;
                int chi = kk * 2 + b_c;
                uint32_t t[4];
                ldsm4(t, wBase + R * 128 + ((chi ^ (R & 7)) * 16));
                wh[2 * np][0] = t[0]; wh[2 * np][1] = t[1];
                wh[2 * np + 1][0] = t[2]; wh[2 * np + 1][1] = t[3];
                ldsm4(t, wBase + R * 128 + (((chi + 4) ^ (R & 7)) * 16));
                wl[2 * np][0] = t[0]; wl[2 * np][1] = t[1];
                wl[2 * np + 1][0] = t[2]; wl[2 * np + 1][1] = t[3];
            }
#pragma unroll
            for (int mf = 0; mf < 4; mf++)
#pragma unroll
                for (int nf = 0; nf < 4; nf++) {
                    mma16816(acc[mf][nf], ah[mf], wh[nf]);
                    mma16816(acc[mf][nf], ah[mf], wl[nf]);
                    mma16816(acc[mf][nf], al[mf], wh[nf]);
                }
        }
    }

    // epilogue
#pragma unroll
    for (int mf = 0; mf < 4; mf++)
#pragma unroll
        for (int nf = 0; nf < 4; nf++) {
            int row0 = bm + wm * 64 + mf * 16 + (lane >> 2);
            int col  = bn + wn * 32 + nf * 8 + (lane & 3) * 2;
            float* c = acc[mf][nf];
            *(float2*)(C + (size_t)row0 * N + col)       = make_float2(c[0], c[1]);
            *(float2*)(C + (size_t)(row0 + 8) * N + col) = make_float2(c[2], c[3]);
        }
}

// ---------------------------------------------------------------------------
// Elementwise: gate+ve on V, rope+rmsnorm(*1.2) on Q and K.
// ---------------------------------------------------------------------------
__global__ __launch_bounds__(256)
void ew_kernel(const float* __restrict__ x,
               const float* __restrict__ ve,
               const float* __restrict__ cosb,
               const float* __restrict__ sinb,
               const float* __restrict__ Wgate)
{
    const int token = blockIdx.x;
    const int s = token % S_;
    const int tid = threadIdx.x;

    __shared__ float gate_s[NKV_];
    __shared__ float cs[32], sn[32];

    if (tid < 32) {
        cs[tid] = cosb[s * 32 + tid];
        sn[tid] = sinb[s * 32 + tid];
    }
    if (tid >= 32 && tid < 32 + NKV_) {
        int kv = tid - 32;
        float acc = 0.f;
#pragma unroll
        for (int c = 0; c < GATE_CH_; c++)
            acc += x[(size_t)token * E_ + c] * Wgate[kv * GATE_CH_ + c];
        gate_s[kv] = 3.f / (1.f + expf(-acc));
    }
    __syncthreads();

    {
        int kv = tid >> 6;
        float g = gate_s[kv];
        size_t idx = (size_t)token * (NKV_ * HD_) + tid;
        g_v[idx] += g * ve[idx];
    }

    const int warp = tid >> 5, lane = tid & 31;
    const float c = cs[lane], si = sn[lane];

    for (int hh = warp; hh < NH_ + NKV_; hh += 8) {
        float* base;
        if (hh < NH_) base = g_q + (size_t)token * (NH_ * HD_) + hh * HD_;
        else          base = g_k + (size_t)token * (NKV_ * HD_) + (hh - NH_) * HD_;

        float x1 = base[lane];
        float x2 = base[lane + 32];
        float o1 =  x1 * c  + x2 * si;
        float o2 = -x1 * si + x2 * c;

        float ss = o1 * o1 + o2 * o2;
#pragma unroll
        for (int o = 16; o > 0; o >>= 1)
            ss += __shfl_xor_sync(0xffffffffu, ss, o);
        float r = rsqrtf(ss * (1.f / HD_) + 1.1920929e-7f) * 1.2f;
        base[lane]      = o1 * r;
        base[lane + 32] = o2 * r;
    }
}

// ---------------------------------------------------------------------------
// Flash attention, fp32 (unchanged from the passing baseline)
// ---------------------------------------------------------------------------
__global__ __launch_bounds__(64)
void attn_kernel()
{
    const int qt = blockIdx.x;
    const int bh = blockIdx.y;
    const int b = bh / NH_, h = bh % NH_;
    const int kvh = h / (NH_ / NKV_);

    __shared__ float Ks[64 * 64];
    __shared__ float Vs[64 * 64];
    __shared__ float Ss[64 * 64];

    const int tid = threadIdx.x;
    const int qrow = qt * 64 + tid;

    float qreg[64];
    {
        const float4* qp = (const float4*)(g_q + (((size_t)(b * S_ + qrow)) * NH_ + h) * HD_);
#pragma unroll
        for (int i = 0; i < 16; i++) {
            float4 t = qp[i];
            qreg[4 * i + 0] = t.x; qreg[4 * i + 1] = t.y;
            qreg[4 * i + 2] = t.z; qreg[4 * i + 3] = t.w;
        }
    }

    float m = -INFINITY, l = 0.f;
    float acc[64];
#pragma unroll
    for (int d = 0; d < 64; d++) acc[d] = 0.f;

    for (int t = 0; t <= qt; t++) {
        __syncthreads();
        for (int idx = tid; idx < 64 * 16; idx += 64) {
            int r = idx >> 4, c4 = idx & 15;
            size_t gbase = (((size_t)(b * S_ + t * 64 + r)) * NKV_ + kvh) * HD_;
            ((float4*)Ks)[r * 16 + c4] = ((const float4*)(g_k + gbase))[c4];
            ((float4*)Vs)[r * 16 + c4] = ((const float4*)(g_v + gbase))[c4];
        }
        __syncthreads();

        const int kmax = (t == qt) ? (tid + 1) : 64;

        float tmax = -INFINITY;
        for (int j = 0; j < 64; j++) {
            float sdot = 0.f;
            const float4* kr = (const float4*)(Ks + j * 64);
#pragma unroll
            for (int i = 0; i < 16; i++) {
                float4 k4 = kr[i];
                sdot += qreg[4 * i + 0] * k4.x + qreg[4 * i + 1] * k4.y
                      + qreg[4 * i + 2] * k4.z + qreg[4 * i + 3] * k4.w;
            }
            sdot *= 0.125f;
            if (j >= kmax) sdot = -INFINITY;
            Ss[j * 64 + tid] = sdot;
            tmax = fmaxf(tmax, sdot);
        }

        float mnew = fmaxf(m, tmax);
        float corr = expf(m - mnew);
        l *= corr;
#pragma unroll
        for (int d = 0; d < 64; d++) acc[d] *= corr;

        for (int j = 0; j < 64; j++) {
            float p = expf(Ss[j * 64 + tid] - mnew);
            l += p;
            const float4* vr = (const float4*)(Vs + j * 64);
#pragma unroll
            for (int i = 0; i < 16; i++) {
                float4 v4 = vr[i];
                acc[4 * i + 0] += p * v4.x; acc[4 * i + 1] += p * v4.y;
                acc[4 * i + 2] += p * v4.z; acc[4 * i + 3] += p * v4.w;
            }
        }
        m = mnew;
    }

    const float inv = 1.f / l;
    float4* yo = (float4*)(g_y + (size_t)(b * S_ + qrow) * (NH_ * HD_) + h * HD_);
#pragma unroll
    for (int i = 0; i < 16; i++)
        yo[i] = make_float4(acc[4 * i + 0] * inv, acc[4 * i + 1] * inv,
                            acc[4 * i + 2] * inv, acc[4 * i + 3] * inv);
}

// ---------------------------------------------------------------------------
// launch — inputs: 0:x 1:ve 2:cos 3:sin 4:attn_mask 5:Wq 6:Wk 7:Wv 8:Wproj 9:Wgate
// ---------------------------------------------------------------------------
extern "C" void kernel_launch(void* const* d_in, const int* in_sizes, int n_in,
                              void* d_out, int out_size)
{
    (void)in_sizes; (void)n_in; (void)out_size;
    const float* x     = (const float*)d_in[0];
    const float* ve    = (const float*)d_in[1];
    const float* cosb  = (const float*)d_in[2];
    const float* sinb  = (const float*)d_in[3];
    const float* Wq    = (const float*)d_in[5];
    const float* Wk    = (const float*)d_in[6];
    const float* Wv    = (const float*)d_in[7];
    const float* Wproj = (const float*)d_in[8];
    const float* Wgate = (const float*)d_in[9];
    float* out = (float*)d_out;

    float *qp, *kp, *vp, *yp;
    cudaGetSymbolAddress((void**)&qp, g_q);
    cudaGetSymbolAddress((void**)&kp, g_k);
    cudaGetSymbolAddress((void**)&vp, g_v);
    cudaGetSymbolAddress((void**)&yp, g_y);
    __nv_bfloat16 *xh, *xl, *yh, *yl, *wh, *wl;
    cudaGetSymbolAddress((void**)&xh, g_xh);
    cudaGetSymbolAddress((void**)&xl, g_xl);
    cudaGetSymbolAddress((void**)&yh, g_yh);
    cudaGetSymbolAddress((void**)&yl, g_yl);
    cudaGetSymbolAddress((void**)&wh, g_wh);
    cudaGetSymbolAddress((void**)&wl, g_wl);

    // split inputs to bf16 hi/lo
    {
        int n4 = TOKENS * E_ / 4;
        split_kernel<<<(n4 + 255) / 256, 256>>>(x, xh, xl, n4);
        int w4 = 1024 * E_ / 4;
        split_kernel<<<(w4 + 255) / 256, 256>>>(Wq, wh + WQ_OFF, wl + WQ_OFF, w4);
        int kv4 = 256 * E_ / 4;
        split_kernel<<<(kv4 + 255) / 256, 256>>>(Wk, wh + WK_OFF, wl + WK_OFF, kv4);
        split_kernel<<<(kv4 + 255) / 256, 256>>>(Wv, wh + WV_OFF, wl + WV_OFF, kv4);
        split_kernel<<<(w4 + 255) / 256, 256>>>(Wproj, wh + WP_OFF, wl + WP_OFF, w4);
    }

    // QKV projections (tensor cores)
    {
        dim3 gq(1024 / 128, TOKENS / 128);
        gemm_split_kernel<<<gq, 256>>>(xh, xl, wh + WQ_OFF, wl + WQ_OFF, qp,
                                       TOKENS, 1024, E_);
        dim3 gkv(256 / 128, TOKENS / 128);
        gemm_split_kernel<<<gkv, 256>>>(xh, xl, wh + WK_OFF, wl + WK_OFF, kp,
                                        TOKENS, 256, E_);
        gemm_split_kernel<<<gkv, 256>>>(xh, xl, wh + WV_OFF, wl + WV_OFF, vp,
                                        TOKENS, 256, E_);
    }

    // gate + ve, rope + rmsnorm
    ew_kernel<<<TOKENS, 256>>>(x, ve, cosb, sinb, Wgate);

    // causal GQA attention
    {
        dim3 ga(S_ / 64, B_ * NH_);
        attn_kernel<<<ga, 64>>>();
    }

    // output projection (tensor cores)
    {
        int n4 = TOKENS * E_ / 4;
        split_kernel<<<(n4 + 255) / 256, 256>>>(yp, yh, yl, n4);
        dim3 gp(E_ / 128, TOKENS / 128);
        gemm_split_kernel<<<gp, 256>>>(yh, yl, wh + WP_OFF, wl + WP_OFF, out,
                                       TOKENS, E_, E_);
    }
}

// round 4
// speedup vs baseline: 3.7221x; 2.8481x over previous
#include <cuda_runtime.h>
#include <cuda_bf16.h>
#include <math.h>
#include <stdint.h>

#define B_   2
#define S_   2048
#define E_   1024
#define NH_  16
#define NKV_ 4
#define HD_  64
#define GATE_CH_ 12
#define TOKENS (B_ * S_)   // 4096

// ---------------------------------------------------------------------------
// Scratch (device globals: no allocation allowed)
// ---------------------------------------------------------------------------
__device__ float g_q[TOKENS * NH_ * HD_];    // fp32 q from gemm
__device__ float g_k[TOKENS * NKV_ * HD_];
__device__ float g_v[TOKENS * NKV_ * HD_];

// split-bf16 activations
__device__ __nv_bfloat16 g_xh[TOKENS * E_];
__device__ __nv_bfloat16 g_xl[TOKENS * E_];
__device__ __nv_bfloat16 g_qh[TOKENS * NH_ * HD_];
__device__ __nv_bfloat16 g_ql[TOKENS * NH_ * HD_];
__device__ __nv_bfloat16 g_kh[TOKENS * NKV_ * HD_];
__device__ __nv_bfloat16 g_kl[TOKENS * NKV_ * HD_];
__device__ __nv_bfloat16 g_vh[TOKENS * NKV_ * HD_];
__device__ __nv_bfloat16 g_vl[TOKENS * NKV_ * HD_];
__device__ __nv_bfloat16 g_yh[TOKENS * E_];
__device__ __nv_bfloat16 g_yl[TOKENS * E_];
// weights hi/lo: 1024(Wq)+256(Wk)+256(Wv)+1024(Wproj) rows
#define WQ_OFF 0
#define WK_OFF (1024 * E_)
#define WV_OFF (1280 * E_)
#define WP_OFF (1536 * E_)
__device__ __nv_bfloat16 g_wh[2560 * E_];
__device__ __nv_bfloat16 g_wl[2560 * E_];

// ---------------------------------------------------------------------------
// PTX helpers
// ---------------------------------------------------------------------------
__device__ __forceinline__ void ldsm4(uint32_t* r, uint32_t addr)
{
    asm volatile("ldmatrix.sync.aligned.m8n8.x4.shared.b16 {%0,%1,%2,%3}, [%4];"
                 : "=r"(r[0]), "=r"(r[1]), "=r"(r[2]), "=r"(r[3]) : "r"(addr));
}
__device__ __forceinline__ void ldsm4t(uint32_t* r, uint32_t addr)
{
    asm volatile("ldmatrix.sync.aligned.m8n8.x4.trans.shared.b16 {%0,%1,%2,%3}, [%4];"
                 : "=r"(r[0]), "=r"(r[1]), "=r"(r[2]), "=r"(r[3]) : "r"(addr));
}
__device__ __forceinline__ void mma16816(float* c, const uint32_t* a, const uint32_t* b)
{
    asm volatile(
        "mma.sync.aligned.m16n8k16.row.col.f32.bf16.bf16.f32 "
        "{%0,%1,%2,%3},{%4,%5,%6,%7},{%8,%9},{%0,%1,%2,%3};"
        : "+f"(c[0]), "+f"(c[1]), "+f"(c[2]), "+f"(c[3])
        : "r"(a[0]), "r"(a[1]), "r"(a[2]), "r"(a[3]), "r"(b[0]), "r"(b[1]));
}
__device__ __forceinline__ void cpasync16(uint32_t s, const void* g)
{
    asm volatile("cp.async.cg.shared.global [%0], [%1], 16;" :: "r"(s), "l"(g));
}
__device__ __forceinline__ void cpcommit() { asm volatile("cp.async.commit_group;"); }
template<int N> __device__ __forceinline__ void cpwait()
{ asm volatile("cp.async.wait_group %0;" :: "n"(N)); }

__device__ __forceinline__ uint32_t packbf2(float a, float b)
{
    __nv_bfloat162 t = __floats2bfloat162_rn(a, b);
    uint32_t u; memcpy(&u, &t, 4); return u;
}

// ---------------------------------------------------------------------------
// split fp32 -> (hi, lo) bf16
// ---------------------------------------------------------------------------
__global__ __launch_bounds__(256)
void split_kernel(const float* __restrict__ in,
                  __nv_bfloat16* __restrict__ hi,
                  __nv_bfloat16* __restrict__ lo, int n4)
{
    int i = blockIdx.x * blockDim.x + threadIdx.x;
    if (i >= n4) return;
    float4 v = ((const float4*)in)[i];
    float vv[4] = {v.x, v.y, v.z, v.w};
    uint2 hv, lv;
    __nv_bfloat16* hp = (__nv_bfloat16*)&hv;
    __nv_bfloat16* lp = (__nv_bfloat16*)&lv;
#pragma unroll
    for (int j = 0; j < 4; j++) {
        __nv_bfloat16 h = __float2bfloat16(vv[j]);
        hp[j] = h;
        lp[j] = __float2bfloat16(vv[j] - __bfloat162float(h));
    }
    ((uint2*)hi)[i] = hv;
    ((uint2*)lo)[i] = lv;
}

// ---------------------------------------------------------------------------
// Tensor-core GEMM (verified R2): C = (Ah+Al)[M,K] @ (Wh+Wl)[N,K]^T, 3-term
// ---------------------------------------------------------------------------
__global__ __launch_bounds__(256, 1)
void gemm_split_kernel(const __nv_bfloat16* __restrict__ Ah,
                       const __nv_bfloat16* __restrict__ Al,
                       const __nv_bfloat16* __restrict__ Wh,
                       const __nv_bfloat16* __restrict__ Wl,
                       float* __restrict__ C,
                       int M, int N, int K)
{
    __shared__ __align__(16) unsigned char sA[128 * 128];
    __shared__ __align__(16) unsigned char sW[128 * 128];

    const int tid  = threadIdx.x;
    const int lane = tid & 31;
    const int warp = tid >> 5;
    const int wm = warp >> 2;
    const int wn = warp & 3;
    const int bm = blockIdx.y * 128;
    const int bn = blockIdx.x * 128;

    const int lchunk = tid & 7;
    const int lrow0  = tid >> 3;
    const __nv_bfloat16* Asrc = (lchunk < 4) ? Ah : Al;
    const __nv_bfloat16* Wsrc = (lchunk < 4) ? Wh : Wl;
    const int kcoloff = (lchunk & 3) * 8;

    float acc[4][4][4];
#pragma unroll
    for (int i = 0; i < 4; i++)
#pragma unroll
        for (int j = 0; j < 4; j++)
#pragma unroll
            for (int r = 0; r < 4; r++) acc[i][j][r] = 0.f;

    const uint32_t aBase = (uint32_t)__cvta_generic_to_shared(sA);
    const uint32_t wBase = (uint32_t)__cvta_generic_to_shared(sW);

    const int a_r = lane & 15;
    const int a_c = (lane >> 4) & 1;
    const int b_r = ((lane >> 4) & 1) * 8 + (lane & 7);
    const int b_c = (lane >> 3) & 1;

    uint4 pa[4], pw[4];
#pragma unroll
    for (int it = 0; it < 4; it++) {
        int row = lrow0 + it * 32;
        pa[it] = *(const uint4*)(Asrc + (size_t)(bm + row) * K + kcoloff);
        pw[it] = *(const uint4*)(Wsrc + (size_t)(bn + row) * K + kcoloff);
    }

    for (int k0 = 0; k0 < K; k0 += 32) {
        __syncthreads();
#pragma unroll
        for (int it = 0; it < 4; it++) {
            int row = lrow0 + it * 32;
            *(uint4*)(sA + row * 128 + ((lchunk ^ (row & 7)) * 16)) = pa[it];
            *(uint4*)(sW + row * 128 + ((lchunk ^ (row & 7)) * 16)) = pw[it];
        }
        __syncthreads();

        if (k0 + 32 < K) {
#pragma unroll
            for (int it = 0; it < 4; it++) {
                int row = lrow0 + it * 32;
                pa[it] = *(const uint4*)(Asrc + (size_t)(bm + row) * K + k0 + 32 + kcoloff);
                pw[it] = *(const uint4*)(Wsrc + (size_t)(bn + row) * K + k0 + 32 + kcoloff);
            }
        }

#pragma unroll
        for (int kk = 0; kk < 2; kk++) {
            uint32_t ah[4][4], al[4][4], wh[4][2], wl[4][2];
#pragma unroll
            for (int mf = 0; mf < 4; mf++) {
                int R = wm * 64 + mf * 16 + a_r;
                int chi = kk * 2 + a_c;
                ldsm4(ah[mf], aBase + R * 128 + ((chi ^ (R & 7)) * 16));
                ldsm4(al[mf], aBase + R * 128 + (((chi + 4) ^ (R & 7)) * 16));
            }
#pragma unroll
            for (int np = 0; np < 2; np++) {
                int R = wn * 32 + np * 16 + b_r;
                int chi = kk * 2 + b_c;
                uint32_t t[4];
                ldsm4(t, wBase + R * 128 + ((chi ^ (R & 7)) * 16));
                wh[2 * np][0] = t[0]; wh[2 * np][1] = t[1];
                wh[2 * np + 1][0] = t[2]; wh[2 * np + 1][1] = t[3];
                ldsm4(t, wBase + R * 128 + (((chi + 4) ^ (R & 7)) * 16));
                wl[2 * np][0] = t[0]; wl[2 * np][1] = t[1];
                wl[2 * np + 1][0] = t[2]; wl[2 * np + 1][1] = t[3];
            }
#pragma unroll
            for (int mf = 0; mf < 4; mf++)
#pragma unroll
                for (int nf = 0; nf < 4; nf++) {
                    mma16816(acc[mf][nf], ah[mf], wh[nf]);
                    mma16816(acc[mf][nf], ah[mf], wl[nf]);
                    mma16816(acc[mf][nf], al[mf], wh[nf]);
                }
        }
    }

#pragma unroll
    for (int mf = 0; mf < 4; mf++)
#pragma unroll
        for (int nf = 0; nf < 4; nf++) {
            int row0 = bm + wm * 64 + mf * 16 + (lane >> 2);
            int col  = bn + wn * 32 + nf * 8 + (lane & 3) * 2;
            float* c = acc[mf][nf];
            *(float2*)(C + (size_t)row0 * N + col)       = make_float2(c[0], c[1]);
            *(float2*)(C + (size_t)(row0 + 8) * N + col) = make_float2(c[2], c[3]);
        }
}

// ---------------------------------------------------------------------------
// Elementwise: gate+ve on V, rope+rmsnorm(*1.2) on Q,K; emits bf16 hi/lo.
// ---------------------------------------------------------------------------
__global__ __launch_bounds__(256)
void ew_kernel(const float* __restrict__ x,
               const float* __restrict__ ve,
               const float* __restrict__ cosb,
               const float* __restrict__ sinb,
               const float* __restrict__ Wgate)
{
    const int token = blockIdx.x;
    const int s = token % S_;
    const int tid = threadIdx.x;

    __shared__ float gate_s[NKV_];
    __shared__ float cs[32], sn[32];

    if (tid < 32) {
        cs[tid] = cosb[s * 32 + tid];
        sn[tid] = sinb[s * 32 + tid];
    }
    if (tid >= 32 && tid < 32 + NKV_) {
        int kv = tid - 32;
        float acc = 0.f;
#pragma unroll
        for (int c = 0; c < GATE_CH_; c++)
            acc += x[(size_t)token * E_ + c] * Wgate[kv * GATE_CH_ + c];
        gate_s[kv] = 3.f / (1.f + expf(-acc));
    }
    __syncthreads();

    {   // v = v + gate*ve, split
        int kv = tid >> 6;
        float g = gate_s[kv];
        size_t idx = (size_t)token * (NKV_ * HD_) + tid;
        float v = g_v[idx] + g * ve[idx];
        __nv_bfloat16 h = __float2bfloat16(v);
        g_vh[idx] = h;
        g_vl[idx] = __float2bfloat16(v - __bfloat162float(h));
    }

    const int warp = tid >> 5, lane = tid & 31;
    const float c = cs[lane], si = sn[lane];

    for (int hh = warp; hh < NH_ + NKV_; hh += 8) {
        const float* base;
        __nv_bfloat16 *oh, *ol;
        if (hh < NH_) {
            size_t off = (size_t)token * (NH_ * HD_) + hh * HD_;
            base = g_q + off; oh = g_qh + off; ol = g_ql + off;
        } else {
            size_t off = (size_t)token * (NKV_ * HD_) + (hh - NH_) * HD_;
            base = g_k + off; oh = g_kh + off; ol = g_kl + off;
        }

        float x1 = base[lane];
        float x2 = base[lane + 32];
        float o1 =  x1 * c  + x2 * si;
        float o2 = -x1 * si + x2 * c;

        float ss = o1 * o1 + o2 * o2;
#pragma unroll
        for (int o = 16; o > 0; o >>= 1)
            ss += __shfl_xor_sync(0xffffffffu, ss, o);
        float r = rsqrtf(ss * (1.f / HD_) + 1.1920929e-7f) * 1.2f;
        float r1 = o1 * r, r2 = o2 * r;
        __nv_bfloat16 h1 = __float2bfloat16(r1);
        __nv_bfloat16 h2 = __float2bfloat16(r2);
        oh[lane]      = h1;
        oh[lane + 32] = h2;
        ol[lane]      = __float2bfloat16(r1 - __bfloat162float(h1));
        ol[lane + 32] = __float2bfloat16(r2 - __bfloat162float(h2));
    }
}

// ---------------------------------------------------------------------------
// Tensor-core flash attention. 64 q-rows/block, 4 warps (16 rows each),
// 64-key tiles, split-bf16 3-term mma for both QK^T and PV.
// Dynamic smem: Q(16KB) + 2 stages x (K 16KB + V 16KB) = 80KB.
// ---------------------------------------------------------------------------
#define SMQ   0
#define SMSTG 16384
#define STGSZ 32768
#define ATT_SMEM (SMSTG + 2 * STGSZ)

__global__ void __launch_bounds__(128, 2) attn_mma_kernel()
{
    extern __shared__ __align__(16) unsigned char sm[];
    const int qt = (int)gridDim.x - 1 - (int)blockIdx.x;  // longest-first
    const int bh = blockIdx.y;
    const int b = bh / NH_, h = bh % NH_;
    const int kvh = h >> 2;   // NH/NKV = 4

    const int tid = threadIdx.x;
    const int lane = tid & 31;
    const int warp = tid >> 5;

    const uint32_t smBase = (uint32_t)__cvta_generic_to_shared(sm);

    // ---- load Q (hi/lo) into smem, swizzled ----
    {
        const int chunk = tid & 7, row0 = tid >> 3;
#pragma unroll
        for (int it = 0; it < 4; it++) {
            int row = row0 + it * 16;
            size_t g = ((size_t)(b * S_ + qt * 64 + row) * NH_ + h) * HD_ + chunk * 8;
            uint32_t so = row * 128 + ((chunk ^ (row & 7)) * 16);
            *(uint4*)(sm + SMQ + so)        = *(const uint4*)(g_qh + g);
            *(uint4*)(sm + SMQ + 8192 + so) = *(const uint4*)(g_ql + g);
        }
    }

    // ---- issue cp.async for tile 0 ----
    const int chunk = tid & 7, row0 = tid >> 3;
    const int swoff = (chunk ^ (row0 & 7)) * 16;   // row0<16 so row&7 == row0&7 when it even... compute per row below
    (void)swoff;
    {
        uint32_t stg = smBase + SMSTG;
#pragma unroll
        for (int it = 0; it < 4; it++) {
            int row = row0 + it * 16;
            size_t g = ((size_t)(b * S_ + 0 * 64 + row) * NKV_ + kvh) * HD_ + chunk * 8;
            uint32_t so = row * 128 + ((chunk ^ (row & 7)) * 16);
            cpasync16(stg + so,             g_kh + g);
            cpasync16(stg + 8192 + so,      g_kl + g);
            cpasync16(stg + 16384 + so,     g_vh + g);
            cpasync16(stg + 24576 + so,     g_vl + g);
        }
        cpcommit();
    }

    __syncthreads();   // Q smem ready

    // ---- Q fragments in registers ----
    const int a_r = lane & 15;
    const int a_c = (lane >> 4) & 1;
    uint32_t qfh[4][4], qfl[4][4];
    {
        int R = warp * 16 + a_r;
#pragma unroll
        for (int ks = 0; ks < 4; ks++) {
            int chi = ks * 2 + a_c;
            ldsm4(qfh[ks], smBase + SMQ + R * 128 + ((chi ^ (R & 7)) * 16));
            ldsm4(qfl[ks], smBase + SMQ + 8192 + R * 128 + ((chi ^ (R & 7)) * 16));
        }
    }

    const int b_r = ((lane >> 4) & 1) * 8 + (lane & 7);
    const int b_c = (lane >> 3) & 1;
    const int t_grp = lane >> 3, t_off = lane & 7;
    const int tkey = ((t_grp & 1) * 8) + t_off;          // key row within 16
    const int tnc  = t_grp >> 1;                          // n-chunk 0/1

    float yacc[8][4];
#pragma unroll
    for (int nf = 0; nf < 8; nf++)
#pragma unroll
        for (int r = 0; r < 4; r++) yacc[nf][r] = 0.f;
    float m0 = -INFINITY, m1 = -INFINITY, l0 = 0.f, l1 = 0.f;

    const float sc = 0.125f;

    for (int t = 0; t <= qt; t++) {
        // prefetch next tile
        if (t < qt) {
            uint32_t stg = smBase + SMSTG + ((t + 1) & 1) * STGSZ;
#pragma unroll
            for (int it = 0; it < 4; it++) {
                int row = row0 + it * 16;
                size_t g = ((size_t)(b * S_ + (t + 1) * 64 + row) * NKV_ + kvh) * HD_ + chunk * 8;
                uint32_t so = row * 128 + ((chunk ^ (row & 7)) * 16);
                cpasync16(stg + so,         g_kh + g);
                cpasync16(stg + 8192 + so,  g_kl + g);
                cpasync16(stg + 16384 + so, g_vh + g);
                cpasync16(stg + 24576 + so, g_vl + g);
            }
            cpcommit();
            cpwait<1>();
        } else {
            cpwait<0>();
        }
        __syncthreads();

        const uint32_t sK  = smBase + SMSTG + (t & 1) * STGSZ;
        const uint32_t sKl = sK + 8192;
        const uint32_t sV  = sK + 16384;
        const uint32_t sVl = sK + 24576;

        // ---- scores S = Q K^T ----
        float s[8][4];
#pragma unroll
        for (int nf = 0; nf < 8; nf++)
#pragma unroll
            for (int r = 0; r < 4; r++) s[nf][r] = 0.f;

#pragma unroll
        for (int ks = 0; ks < 4; ks++) {
            uint32_t kbh[8][2], kbl[8][2];
#pragma unroll
            for (int np = 0; np < 4; np++) {
                int R = np * 16 + b_r;
                int chi = ks * 2 + b_c;
                uint32_t tt[4];
                ldsm4(tt, sK + R * 128 + ((chi ^ (R & 7)) * 16));
                kbh[2 * np][0] = tt[0]; kbh[2 * np][1] = tt[1];
                kbh[2 * np + 1][0] = tt[2]; kbh[2 * np + 1][1] = tt[3];
                ldsm4(tt, sKl + R * 128 + ((chi ^ (R & 7)) * 16));
                kbl[2 * np][0] = tt[0]; kbl[2 * np][1] = tt[1];
                kbl[2 * np + 1][0] = tt[2]; kbl[2 * np + 1][1] = tt[3];
            }
#pragma unroll
            for (int nf = 0; nf < 8; nf++) {
                mma16816(s[nf], qfh[ks], kbh[nf]);
                mma16816(s[nf], qfh[ks], kbl[nf]);
                mma16816(s[nf], qfl[ks], kbh[nf]);
            }
        }

        // ---- causal mask (diagonal tile only) ----
        if (t == qt) {
            int r0q = warp * 16 + (lane >> 2);
#pragma unroll
            for (int nf = 0; nf < 8; nf++) {
                int c0 = nf * 8 + (lane & 3) * 2;
                if (c0 > r0q)          s[nf][0] = -INFINITY;
                if (c0 + 1 > r0q)      s[nf][1] = -INFINITY;
                if (c0 > r0q + 8)      s[nf][2] = -INFINITY;
                if (c0 + 1 > r0q + 8)  s[nf][3] = -INFINITY;
            }
        }

        // ---- online softmax ----
        float tm0 = -INFINITY, tm1 = -INFINITY;
#pragma unroll
        for (int nf = 0; nf < 8; nf++) {
            tm0 = fmaxf(tm0, fmaxf(s[nf][0], s[nf][1]));
            tm1 = fmaxf(tm1, fmaxf(s[nf][2], s[nf][3]));
        }
        tm0 = fmaxf(tm0, __shfl_xor_sync(0xffffffffu, tm0, 1));
        tm0 = fmaxf(tm0, __shfl_xor_sync(0xffffffffu, tm0, 2));
        tm1 = fmaxf(tm1, __shfl_xor_sync(0xffffffffu, tm1, 1));
        tm1 = fmaxf(tm1, __shfl_xor_sync(0xffffffffu, tm1, 2));

        float mn0 = fmaxf(m0, tm0), mn1 = fmaxf(m1, tm1);
        float cr0 = __expf((m0 - mn0) * sc);
        float cr1 = __expf((m1 - mn1) * sc);
        l0 *= cr0; l1 *= cr1;
#pragma unroll
        for (int nf = 0; nf < 8; nf++) {
            yacc[nf][0] *= cr0; yacc[nf][1] *= cr0;
            yacc[nf][2] *= cr1; yacc[nf][3] *= cr1;
        }

#pragma unroll
        for (int nf = 0; nf < 8; nf++) {
            s[nf][0] = __expf((s[nf][0] - mn0) * sc);
            s[nf][1] = __expf((s[nf][1] - mn0) * sc);
            s[nf][2] = __expf((s[nf][2] - mn1) * sc);
            s[nf][3] = __expf((s[nf][3] - mn1) * sc);
            l0 += s[nf][0] + s[nf][1];
            l1 += s[nf][2] + s[nf][3];
        }
        m0 = mn0; m1 = mn1;

        // ---- y += P V : repack P accumulators into A-fragments ----
#pragma unroll
        for (int ks = 0; ks < 4; ks++) {
            uint32_t ph[4], pl[4];
            {
                float* e = s[2 * ks];
                float* o = s[2 * ks + 1];
                float eh0 = __bfloat162float(__float2bfloat16(e[0]));
                float eh1 = __bfloat162float(__float2bfloat16(e[1]));
                float eh2 = __bfloat162float(__float2bfloat16(e[2]));
                float eh3 = __bfloat162float(__float2bfloat16(e[3]));
                float oh0 = __bfloat162float(__float2bfloat16(o[0]));
                float oh1 = __bfloat162float(__float2bfloat16(o[1]));
                float oh2 = __bfloat162float(__float2bfloat16(o[2]));
                float oh3 = __bfloat162float(__float2bfloat16(o[3]));
                ph[0] = packbf2(eh0, eh1); ph[1] = packbf2(eh2, eh3);
                ph[2] = packbf2(oh0, oh1); ph[3] = packbf2(oh2, oh3);
                pl[0] = packbf2(e[0] - eh0, e[1] - eh1);
                pl[1] = packbf2(e[2] - eh2, e[3] - eh3);
                pl[2] = packbf2(o[0] - oh0, o[1] - oh1);
                pl[3] = packbf2(o[2] - oh2, o[3] - oh3);
            }
            int keyr = ks * 16 + tkey;
#pragma unroll
            for (int np = 0; np < 4; np++) {
                int nch = np * 2 + tnc;
                uint32_t vh[4], vl[4];
                ldsm4t(vh, sV  + keyr * 128 + ((nch ^ (keyr & 7)) * 16));
                ldsm4t(vl, sVl + keyr * 128 + ((nch ^ (keyr & 7)) * 16));
                uint32_t bh0[2] = {vh[0], vh[1]}, bh1[2] = {vh[2], vh[3]};
                uint32_t bl0[2] = {vl[0], vl[1]}, bl1[2] = {vl[2], vl[3]};
                mma16816(yacc[2 * np],     ph, bh0);
                mma16816(yacc[2 * np],     ph, bl0);
                mma16816(yacc[2 * np],     pl, bh0);
                mma16816(yacc[2 * np + 1], ph, bh1);
                mma16816(yacc[2 * np + 1], ph, bl1);
                mma16816(yacc[2 * np + 1], pl, bh1);
            }
        }
        __syncthreads();
    }

    // ---- finalize: reduce l across lane quad, normalize, store hi/lo ----
    l0 += __shfl_xor_sync(0xffffffffu, l0, 1);
    l0 += __shfl_xor_sync(0xffffffffu, l0, 2);
    l1 += __shfl_xor_sync(0xffffffffu, l1, 1);
    l1 += __shfl_xor_sync(0xffffffffu, l1, 2);
    float inv0 = 1.f / l0, inv1 = 1.f / l1;

    int tok0 = b * S_ + qt * 64 + warp * 16 + (lane >> 2);
    int tok1 = tok0 + 8;
#pragma unroll
    for (int nf = 0; nf < 8; nf++) {
        int col = h * 64 + nf * 8 + (lane & 3) * 2;
        float y0 = yacc[nf][0] * inv0, y1 = yacc[nf][1] * inv0;
        float y2 = yacc[nf][2] * inv1, y3 = yacc[nf][3] * inv1;
        float h0 = __bfloat162float(__float2bfloat16(y0));
        float h1 = __bfloat162float(__float2bfloat16(y1));
        float h2 = __bfloat162float(__float2bfloat16(y2));
        float h3 = __bfloat162float(__float2bfloat16(y3));
        *(uint32_t*)(g_yh + (size_t)tok0 * E_ + col) = packbf2(h0, h1);
        *(uint32_t*)(g_yl + (size_t)tok0 * E_ + col) = packbf2(y0 - h0, y1 - h1);
        *(uint32_t*)(g_yh + (size_t)tok1 * E_ + col) = packbf2(h2, h3);
        *(uint32_t*)(g_yl + (size_t)tok1 * E_ + col) = packbf2(y2 - h2, y3 - h3);
    }
}

// ---------------------------------------------------------------------------
// launch — inputs: 0:x 1:ve 2:cos 3:sin 4:attn_mask 5:Wq 6:Wk 7:Wv 8:Wproj 9:Wgate
// ---------------------------------------------------------------------------
extern "C" void kernel_launch(void* const* d_in, const int* in_sizes, int n_in,
                              void* d_out, int out_size)
{
    (void)in_sizes; (void)n_in; (void)out_size;
    const float* x     = (const float*)d_in[0];
    const float* ve    = (const float*)d_in[1];
    const float* cosb  = (const float*)d_in[2];
    const float* sinb  = (const float*)d_in[3];
    const float* Wq    = (const float*)d_in[5];
    const float* Wk    = (const float*)d_in[6];
    const float* Wv    = (const float*)d_in[7];
    const float* Wproj = (const float*)d_in[8];
    const float* Wgate = (const float*)d_in[9];
    float* out = (float*)d_out;

    float *qp, *kp, *vp;
    cudaGetSymbolAddress((void**)&qp, g_q);
    cudaGetSymbolAddress((void**)&kp, g_k);
    cudaGetSymbolAddress((void**)&vp, g_v);
    __nv_bfloat16 *xh, *xl, *yh, *yl, *wh, *wl;
    cudaGetSymbolAddress((void**)&xh, g_xh);
    cudaGetSymbolAddress((void**)&xl, g_xl);
    cudaGetSymbolAddress((void**)&yh, g_yh);
    cudaGetSymbolAddress((void**)&yl, g_yl);
    cudaGetSymbolAddress((void**)&wh, g_wh);
    cudaGetSymbolAddress((void**)&wl, g_wl);

    static int smem_set = 0;
    if (!smem_set) {
        cudaFuncSetAttribute(attn_mma_kernel,
                             cudaFuncAttributeMaxDynamicSharedMemorySize, ATT_SMEM);
        smem_set = 1;
    }

    // split inputs to bf16 hi/lo
    {
        int n4 = TOKENS * E_ / 4;
        split_kernel<<<(n4 + 255) / 256, 256>>>(x, xh, xl, n4);
        int w4 = 1024 * E_ / 4;
        split_kernel<<<(w4 + 255) / 256, 256>>>(Wq, wh + WQ_OFF, wl + WQ_OFF, w4);
        int kv4 = 256 * E_ / 4;
        split_kernel<<<(kv4 + 255) / 256, 256>>>(Wk, wh + WK_OFF, wl + WK_OFF, kv4);
        split_kernel<<<(kv4 + 255) / 256, 256>>>(Wv, wh + WV_OFF, wl + WV_OFF, kv4);
        split_kernel<<<(w4 + 255) / 256, 256>>>(Wproj, wh + WP_OFF, wl + WP_OFF, w4);
    }

    // QKV projections (tensor cores)
    {
        dim3 gq(1024 / 128, TOKENS / 128);
        gemm_split_kernel<<<gq, 256>>>(xh, xl, wh + WQ_OFF, wl + WQ_OFF, qp,
                                       TOKENS, 1024, E_);
        dim3 gkv(256 / 128, TOKENS / 128);
        gemm_split_kernel<<<gkv, 256>>>(xh, xl, wh + WK_OFF, wl + WK_OFF, kp,
                                        TOKENS, 256, E_);
        gemm_split_kernel<<<gkv, 256>>>(xh, xl, wh + WV_OFF, wl + WV_OFF, vp,
                                        TOKENS, 256, E_);
    }

    // gate + ve, rope + rmsnorm (emits bf16 hi/lo q,k,v)
    ew_kernel<<<TOKENS, 256>>>(x, ve, cosb, sinb, Wgate);

    // tensor-core flash attention (emits bf16 hi/lo y)
    {
        dim3 ga(S_ / 64, B_ * NH_);
        attn_mma_kernel<<<ga, 128, ATT_SMEM>>>();
    }

    // output projection (tensor cores)
    {
        dim3 gp(E_ / 128, TOKENS / 128);
        gemm_split_kernel<<<gp, 256>>>(yh, yl, wh + WP_OFF, wl + WP_OFF, out,
                                       TOKENS, E_, E_);
    }
}

// round 5
// speedup vs baseline: 4.1840x; 1.1241x over previous
#include <cuda_runtime.h>
#include <cuda_bf16.h>
#include <math.h>
#include <stdint.h>

#define B_   2
#define S_   2048
#define E_   1024
#define NH_  16
#define NKV_ 4
#define HD_  64
#define GATE_CH_ 12
#define TOKENS (B_ * S_)   // 4096

// ---------------------------------------------------------------------------
// Scratch (device globals: no allocation allowed)
// ---------------------------------------------------------------------------
__device__ float g_qkv[TOKENS * 1536];           // fused QKV output (q|k|v)

__device__ __nv_bfloat16 g_xh[TOKENS * E_];
__device__ __nv_bfloat16 g_xl[TOKENS * E_];
__device__ __nv_bfloat16 g_qh[TOKENS * NH_ * HD_];
__device__ __nv_bfloat16 g_ql[TOKENS * NH_ * HD_];
__device__ __nv_bfloat16 g_kh[TOKENS * NKV_ * HD_];
__device__ __nv_bfloat16 g_kl[TOKENS * NKV_ * HD_];
__device__ __nv_bfloat16 g_vh[TOKENS * NKV_ * HD_];
__device__ __nv_bfloat16 g_vl[TOKENS * NKV_ * HD_];
__device__ __nv_bfloat16 g_yh[TOKENS * E_];
__device__ __nv_bfloat16 g_yl[TOKENS * E_];
// weight rows: [Wq 0..1024 | Wk 1024..1280 | Wv 1280..1536 | Wproj 1536..2560]
#define WP_OFF (1536 * E_)
__device__ __nv_bfloat16 g_wh[2560 * E_];
__device__ __nv_bfloat16 g_wl[2560 * E_];

// ---------------------------------------------------------------------------
// PTX helpers
// ---------------------------------------------------------------------------
__device__ __forceinline__ void ldsm4(uint32_t* r, uint32_t addr)
{
    asm volatile("ldmatrix.sync.aligned.m8n8.x4.shared.b16 {%0,%1,%2,%3}, [%4];"
                 : "=r"(r[0]), "=r"(r[1]), "=r"(r[2]), "=r"(r[3]) : "r"(addr));
}
__device__ __forceinline__ void ldsm4t(uint32_t* r, uint32_t addr)
{
    asm volatile("ldmatrix.sync.aligned.m8n8.x4.trans.shared.b16 {%0,%1,%2,%3}, [%4];"
                 : "=r"(r[0]), "=r"(r[1]), "=r"(r[2]), "=r"(r[3]) : "r"(addr));
}
__device__ __forceinline__ void mma16816(float* c, const uint32_t* a, const uint32_t* b)
{
    asm volatile(
        "mma.sync.aligned.m16n8k16.row.col.f32.bf16.bf16.f32 "
        "{%0,%1,%2,%3},{%4,%5,%6,%7},{%8,%9},{%0,%1,%2,%3};"
        : "+f"(c[0]), "+f"(c[1]), "+f"(c[2]), "+f"(c[3])
        : "r"(a[0]), "r"(a[1]), "r"(a[2]), "r"(a[3]), "r"(b[0]), "r"(b[1]));
}
__device__ __forceinline__ void cpasync16(uint32_t s, const void* g)
{
    asm volatile("cp.async.cg.shared.global [%0], [%1], 16;" :: "r"(s), "l"(g));
}
__device__ __forceinline__ void cpcommit() { asm volatile("cp.async.commit_group;"); }
template<int N> __device__ __forceinline__ void cpwait()
{ asm volatile("cp.async.wait_group %0;" :: "n"(N)); }

__device__ __forceinline__ uint32_t packbf2(float a, float b)
{
    __nv_bfloat162 t = __floats2bfloat162_rn(a, b);
    uint32_t u; memcpy(&u, &t, 4); return u;
}

// ---------------------------------------------------------------------------
// split fp32 -> (hi, lo) bf16
// ---------------------------------------------------------------------------
__global__ __launch_bounds__(256)
void split_kernel(const float* __restrict__ in,
                  __nv_bfloat16* __restrict__ hi,
                  __nv_bfloat16* __restrict__ lo, int n4)
{
    int i = blockIdx.x * blockDim.x + threadIdx.x;
    if (i >= n4) return;
    float4 v = ((const float4*)in)[i];
    float vv[4] = {v.x, v.y, v.z, v.w};
    uint2 hv, lv;
    __nv_bfloat16* hp = (__nv_bfloat16*)&hv;
    __nv_bfloat16* lp = (__nv_bfloat16*)&lv;
#pragma unroll
    for (int j = 0; j < 4; j++) {
        __nv_bfloat16 h = __float2bfloat16(vv[j]);
        hp[j] = h;
        lp[j] = __float2bfloat16(vv[j] - __bfloat162float(h));
    }
    ((uint2*)hi)[i] = hv;
    ((uint2*)lo)[i] = lv;
}

// all four weight matrices -> one split buffer, one launch
__global__ __launch_bounds__(256)
void splitw_kernel(const float* __restrict__ Wq, const float* __restrict__ Wk,
                   const float* __restrict__ Wv, const float* __restrict__ Wp)
{
    int i = blockIdx.x * blockDim.x + threadIdx.x;  // quad id
    int e0 = i * 4;
    if (e0 >= 2560 * E_) return;
    int row = e0 >> 10, col = e0 & 1023;
    const float* src;
    if      (row < 1024) src = Wq + (size_t)row * E_ + col;
    else if (row < 1280) src = Wk + (size_t)(row - 1024) * E_ + col;
    else if (row < 1536) src = Wv + (size_t)(row - 1280) * E_ + col;
    else                 src = Wp + (size_t)(row - 1536) * E_ + col;
    float4 v = *(const float4*)src;
    float vv[4] = {v.x, v.y, v.z, v.w};
    uint2 hv, lv;
    __nv_bfloat16* hp = (__nv_bfloat16*)&hv;
    __nv_bfloat16* lp = (__nv_bfloat16*)&lv;
#pragma unroll
    for (int j = 0; j < 4; j++) {
        __nv_bfloat16 h = __float2bfloat16(vv[j]);
        hp[j] = h;
        lp[j] = __float2bfloat16(vv[j] - __bfloat162float(h));
    }
    ((uint2*)g_wh)[i] = hv;
    ((uint2*)g_wl)[i] = lv;
}

// ---------------------------------------------------------------------------
// Tensor-core GEMM, 3-stage cp.async pipeline.
// C = (Ah+Al)[M,K] @ (Wh+Wl)[N,K]^T   (3-term split bf16)
// tile 128x128, BK=32, 256 thr (8 warps, 2x4), warp tile 64x32.
// Stage layout: A at +0 (16KB), W at +16KB; row = 128B [hi k0..31 | lo k0..31],
// XOR-(row&7) 16B-chunk swizzle. One __syncthreads per k-iter.
// ---------------------------------------------------------------------------
#define GSTG 32768
#define GEMM_SMEM (3 * GSTG)   // 96 KB

__global__ __launch_bounds__(256, 1)
void gemm_split_pipe(const __nv_bfloat16* __restrict__ Ah,
                     const __nv_bfloat16* __restrict__ Al,
                     const __nv_bfloat16* __restrict__ Wh,
                     const __nv_bfloat16* __restrict__ Wl,
                     float* __restrict__ C,
                     int M, int N, int K)
{
    extern __shared__ __align__(16) unsigned char gsm[];
    const uint32_t smBase = (uint32_t)__cvta_generic_to_shared(gsm);

    const int tid  = threadIdx.x;
    const int lane = tid & 31;
    const int warp = tid >> 5;
    const int wm = warp >> 2;
    const int wn = warp & 3;
    const int bm = blockIdx.y * 128;
    const int bn = blockIdx.x * 128;

    const int lchunk = tid & 7;
    const int lrow0  = tid >> 3;
    const __nv_bfloat16* Asrc = (lchunk < 4) ? Ah : Al;
    const __nv_bfloat16* Wsrc = (lchunk < 4) ? Wh : Wl;
    const int kcoloff = (lchunk & 3) * 8;

    const int niter = K >> 5;

    auto issue_stage = [&](int it) {
        uint32_t base = smBase + (it % 3) * GSTG;
        int k0 = it * 32;
#pragma unroll
        for (int r = 0; r < 4; r++) {
            int row = lrow0 + r * 32;
            uint32_t so = row * 128 + ((lchunk ^ (row & 7)) * 16);
            cpasync16(base + so,
                      Asrc + (size_t)(bm + row) * K + k0 + kcoloff);
            cpasync16(base + 16384 + so,
                      Wsrc + (size_t)(bn + row) * K + k0 + kcoloff);
        }
    };

    issue_stage(0); cpcommit();
    issue_stage(1); cpcommit();

    float acc[4][4][4];
#pragma unroll
    for (int i = 0; i < 4; i++)
#pragma unroll
        for (int j = 0; j < 4; j++)
#pragma unroll
            for (int r = 0; r < 4; r++) acc[i][j][r] = 0.f;

    const int a_r = lane & 15;
    const int a_c = (lane >> 4) & 1;
    const int b_r = ((lane >> 4) & 1) * 8 + (lane & 7);
    const int b_c = (lane >> 3) & 1;

    for (int i = 0; i < niter; i++) {
        cpwait<1>();
        __syncthreads();
        if (i + 2 < niter) issue_stage(i + 2);
        cpcommit();

        const uint32_t aB = smBase + (i % 3) * GSTG;
        const uint32_t wB = aB + 16384;

#pragma unroll
        for (int kk = 0; kk < 2; kk++) {
            uint32_t ah[4][4], al[4][4], wh[4][2], wl[4][2];
#pragma unroll
            for (int mf = 0; mf < 4; mf++) {
                int R = wm * 64 + mf * 16 + a_r;
                int chi = kk * 2 + a_c;
                ldsm4(ah[mf], aB + R * 128 + ((chi ^ (R & 7)) * 16));
                ldsm4(al[mf], aB + R * 128 + (((chi + 4) ^ (R & 7)) * 16));
            }
#pragma unroll
            for (int np = 0; np < 2; np++) {
                int R = wn * 32 + np * 16 + b_r;
                int chi = kk * 2 + b_c;
                uint32_t t[4];
                ldsm4(t, wB + R * 128 + ((chi ^ (R & 7)) * 16));
                wh[2 * np][0] = t[0]; wh[2 * np][1] = t[1];
                wh[2 * np + 1][0] = t[2]; wh[2 * np + 1][1] = t[3];
                ldsm4(t, wB + R * 128 + (((chi + 4) ^ (R & 7)) * 16));
                wl[2 * np][0] = t[0]; wl[2 * np][1] = t[1];
                wl[2 * np + 1][0] = t[2]; wl[2 * np + 1][1] = t[3];
            }
#pragma unroll
            for (int mf = 0; mf < 4; mf++)
#pragma unroll
                for (int nf = 0; nf < 4; nf++) {
                    mma16816(acc[mf][nf], ah[mf], wh[nf]);
                    mma16816(acc[mf][nf], ah[mf], wl[nf]);
                    mma16816(acc[mf][nf], al[mf], wh[nf]);
                }
        }
    }

#pragma unroll
    for (int mf = 0; mf < 4; mf++)
#pragma unroll
        for (int nf = 0; nf < 4; nf++) {
            int row0 = bm + wm * 64 + mf * 16 + (lane >> 2);
            int col  = bn + wn * 32 + nf * 8 + (lane & 3) * 2;
            float* c = acc[mf][nf];
            *(float2*)(C + (size_t)row0 * N + col)       = make_float2(c[0], c[1]);
            *(float2*)(C + (size_t)(row0 + 8) * N + col) = make_float2(c[2], c[3]);
        }
}

// ---------------------------------------------------------------------------
// Elementwise: gate+ve on V, rope+rmsnorm(*1.2) on Q,K; reads fused g_qkv,
// emits bf16 hi/lo.
// ---------------------------------------------------------------------------
__global__ __launch_bounds__(256)
void ew_kernel(const float* __restrict__ x,
               const float* __restrict__ ve,
               const float* __restrict__ cosb,
               const float* __restrict__ sinb,
               const float* __restrict__ Wgate)
{
    const int token = blockIdx.x;
    const int s = token % S_;
    const int tid = threadIdx.x;

    __shared__ float gate_s[NKV_];
    __shared__ float cs[32], sn[32];

    if (tid < 32) {
        cs[tid] = cosb[s * 32 + tid];
        sn[tid] = sinb[s * 32 + tid];
    }
    if (tid >= 32 && tid < 32 + NKV_) {
        int kv = tid - 32;
        float acc = 0.f;
#pragma unroll
        for (int c = 0; c < GATE_CH_; c++)
            acc += x[(size_t)token * E_ + c] * Wgate[kv * GATE_CH_ + c];
        gate_s[kv] = 3.f / (1.f + expf(-acc));
    }
    __syncthreads();

    {   // v = v + gate*ve, split
        int kv = tid >> 6;
        float g = gate_s[kv];
        float v = g_qkv[(size_t)token * 1536 + 1280 + tid] + g * ve[(size_t)token * 256 + tid];
        size_t idx = (size_t)token * (NKV_ * HD_) + tid;
        __nv_bfloat16 h = __float2bfloat16(v);
        g_vh[idx] = h;
        g_vl[idx] = __float2bfloat16(v - __bfloat162float(h));
    }

    const int warp = tid >> 5, lane = tid & 31;
    const float c = cs[lane], si = sn[lane];

    for (int hh = warp; hh < NH_ + NKV_; hh += 8) {
        const float* base;
        __nv_bfloat16 *oh, *ol;
        if (hh < NH_) {
            base = g_qkv + (size_t)token * 1536 + hh * HD_;
            size_t off = (size_t)token * (NH_ * HD_) + hh * HD_;
            oh = g_qh + off; ol = g_ql + off;
        } else {
            int kv = hh - NH_;
            base = g_qkv + (size_t)token * 1536 + 1024 + kv * HD_;
            size_t off = (size_t)token * (NKV_ * HD_) + kv * HD_;
            oh = g_kh + off; ol = g_kl + off;
        }

        float x1 = base[lane];
        float x2 = base[lane + 32];
        float o1 =  x1 * c  + x2 * si;
        float o2 = -x1 * si + x2 * c;

        float ss = o1 * o1 + o2 * o2;
#pragma unroll
        for (int o = 16; o > 0; o >>= 1)
            ss += __shfl_xor_sync(0xffffffffu, ss, o);
        float r = rsqrtf(ss * (1.f / HD_) + 1.1920929e-7f) * 1.2f;
        float r1 = o1 * r, r2 = o2 * r;
        __nv_bfloat16 h1 = __float2bfloat16(r1);
        __nv_bfloat16 h2 = __float2bfloat16(r2);
        oh[lane]      = h1;
        oh[lane + 32] = h2;
        ol[lane]      = __float2bfloat16(r1 - __bfloat162float(h1));
        ol[lane + 32] = __float2bfloat16(r2 - __bfloat162float(h2));
    }
}

// ---------------------------------------------------------------------------
// Tensor-core flash attention. 128 q-rows/block, 8 warps (16 rows each),
// 64-key tiles, split-bf16 3-term mma for QK^T and PV.
// smem: Q hi 16K + Q lo 16K + 2 stages x 32K = 96KB. 256 threads.
// ---------------------------------------------------------------------------
#define ASMQ_L 16384
#define ASMKV  32768
#define ASTG   32768
#define ATT_SMEM (ASMKV + 2 * ASTG)   // 96 KB

__global__ void __launch_bounds__(256, 1) attn_mma_kernel()
{
    extern __shared__ __align__(16) unsigned char sm[];
    const int qt = (int)gridDim.x - 1 - (int)blockIdx.x;  // longest-first
    const int bh = blockIdx.y;
    const int b = bh / NH_, h = bh % NH_;
    const int kvh = h >> 2;

    const int tid = threadIdx.x;
    const int lane = tid & 31;
    const int warp = tid >> 5;          // 0..7

    const uint32_t smBase = (uint32_t)__cvta_generic_to_shared(sm);

    const int chunk = tid & 7;
    const int row0  = tid >> 3;         // 0..31

    // ---- load Q (hi/lo), 128 rows, swizzled ----
#pragma unroll
    for (int it = 0; it < 4; it++) {
        int row = row0 + it * 32;
        size_t g = ((size_t)(b * S_ + qt * 128 + row) * NH_ + h) * HD_ + chunk * 8;
        uint32_t so = row * 128 + ((chunk ^ (row & 7)) * 16);
        *(uint4*)(sm + so)          = *(const uint4*)(g_qh + g);
        *(uint4*)(sm + ASMQ_L + so) = *(const uint4*)(g_ql + g);
    }

    auto issue_kv = [&](int t) {
        uint32_t stg = smBase + ASMKV + (t & 1) * ASTG;
#pragma unroll
        for (int it = 0; it < 2; it++) {
            int row = row0 + it * 32;
            size_t g = ((size_t)(b * S_ + t * 64 + row) * NKV_ + kvh) * HD_ + chunk * 8;
            uint32_t so = row * 128 + ((chunk ^ (row & 7)) * 16);
            cpasync16(stg + so,         g_kh + g);
            cpasync16(stg + 8192 + so,  g_kl + g);
            cpasync16(stg + 16384 + so, g_vh + g);
            cpasync16(stg + 24576 + so, g_vl + g);
        }
        cpcommit();
    };
    issue_kv(0);

    __syncthreads();   // Q ready

    // ---- Q fragments ----
    const int a_r = lane & 15;
    const int a_c = (lane >> 4) & 1;
    uint32_t qfh[4][4], qfl[4][4];
    {
        int R = warp * 16 + a_r;
#pragma unroll
        for (int ks = 0; ks < 4; ks++) {
            int chi = ks * 2 + a_c;
            ldsm4(qfh[ks], smBase + R * 128 + ((chi ^ (R & 7)) * 16));
            ldsm4(qfl[ks], smBase + ASMQ_L + R * 128 + ((chi ^ (R & 7)) * 16));
        }
    }

    const int b_r = ((lane >> 4) & 1) * 8 + (lane & 7);
    const int b_c = (lane >> 3) & 1;
    const int t_grp = lane >> 3, t_off = lane & 7;
    const int tkey = ((t_grp & 1) * 8) + t_off;
    const int tnc  = t_grp >> 1;

    float yacc[8][4];
#pragma unroll
    for (int nf = 0; nf < 8; nf++)
#pragma unroll
        for (int r = 0; r < 4; r++) yacc[nf][r] = 0.f;
    float m0 = -INFINITY, m1 = -INFINITY, l0 = 0.f, l1 = 0.f;

    const float sc = 0.125f;
    const int r0q = qt * 128 + warp * 16 + (lane >> 2);   // global q row (first of pair)
    const int warp_last = qt * 128 + warp * 16 + 15;
    const int tmax = 2 * qt + 1;

    for (int t = 0; t <= tmax; t++) {
        if (t < tmax) { issue_kv(t + 1); cpwait<1>(); }
        else          { cpwait<0>(); }
        __syncthreads();

        const bool skip = warp_last < t * 64;   // warp entirely above this key tile
        if (!skip) {
            const uint32_t sK  = smBase + ASMKV + (t & 1) * ASTG;
            const uint32_t sKl = sK + 8192;
            const uint32_t sV  = sK + 16384;
            const uint32_t sVl = sK + 24576;

            // ---- S = Q K^T ----
            float s[8][4];
#pragma unroll
            for (int nf = 0; nf < 8; nf++)
#pragma unroll
                for (int r = 0; r < 4; r++) s[nf][r] = 0.f;

#pragma unroll
            for (int ks = 0; ks < 4; ks++) {
                uint32_t kbh[8][2], kbl[8][2];
#pragma unroll
                for (int np = 0; np < 4; np++) {
                    int R = np * 16 + b_r;
                    int chi = ks * 2 + b_c;
                    uint32_t tt[4];
                    ldsm4(tt, sK + R * 128 + ((chi ^ (R & 7)) * 16));
                    kbh[2 * np][0] = tt[0]; kbh[2 * np][1] = tt[1];
                    kbh[2 * np + 1][0] = tt[2]; kbh[2 * np + 1][1] = tt[3];
                    ldsm4(tt, sKl + R * 128 + ((chi ^ (R & 7)) * 16));
                    kbl[2 * np][0] = tt[0]; kbl[2 * np][1] = tt[1];
                    kbl[2 * np + 1][0] = tt[2]; kbl[2 * np + 1][1] = tt[3];
                }
#pragma unroll
                for (int nf = 0; nf < 8; nf++) {
                    mma16816(s[nf], qfh[ks], kbh[nf]);
                    mma16816(s[nf], qfh[ks], kbl[nf]);
                    mma16816(s[nf], qfl[ks], kbh[nf]);
                }
            }

            // ---- causal mask (only possible on last two tiles) ----
            if (t >= 2 * qt) {
#pragma unroll
                for (int nf = 0; nf < 8; nf++) {
                    int c0 = t * 64 + nf * 8 + (lane & 3) * 2;
                    if (c0 > r0q)          s[nf][0] = -INFINITY;
                    if (c0 + 1 > r0q)      s[nf][1] = -INFINITY;
                    if (c0 > r0q + 8)      s[nf][2] = -INFINITY;
                    if (c0 + 1 > r0q + 8)  s[nf][3] = -INFINITY;
                }
            }

            // ---- online softmax ----
            float tm0 = -INFINITY, tm1 = -INFINITY;
#pragma unroll
            for (int nf = 0; nf < 8; nf++) {
                tm0 = fmaxf(tm0, fmaxf(s[nf][0], s[nf][1]));
                tm1 = fmaxf(tm1, fmaxf(s[nf][2], s[nf][3]));
            }
            tm0 = fmaxf(tm0, __shfl_xor_sync(0xffffffffu, tm0, 1));
            tm0 = fmaxf(tm0, __shfl_xor_sync(0xffffffffu, tm0, 2));
            tm1 = fmaxf(tm1, __shfl_xor_sync(0xffffffffu, tm1, 1));
            tm1 = fmaxf(tm1, __shfl_xor_sync(0xffffffffu, tm1, 2));

            float mn0 = fmaxf(m0, tm0), mn1 = fmaxf(m1, tm1);
            float cr0 = __expf((m0 - mn0) * sc);
            float cr1 = __expf((m1 - mn1) * sc);
            l0 *= cr0; l1 *= cr1;
#pragma unroll
            for (int nf = 0; nf < 8; nf++) {
                yacc[nf][0] *= cr0; yacc[nf][1] *= cr0;
                yacc[nf][2] *= cr1; yacc[nf][3] *= cr1;
            }
#pragma unroll
            for (int nf = 0; nf < 8; nf++) {
                s[nf][0] = __expf((s[nf][0] - mn0) * sc);
                s[nf][1] = __expf((s[nf][1] - mn0) * sc);
                s[nf][2] = __expf((s[nf][2] - mn1) * sc);
                s[nf][3] = __expf((s[nf][3] - mn1) * sc);
                l0 += s[nf][0] + s[nf][1];
                l1 += s[nf][2] + s[nf][3];
            }
            m0 = mn0; m1 = mn1;

            // ---- y += P V ----
#pragma unroll
            for (int ks = 0; ks < 4; ks++) {
                uint32_t ph[4], pl[4];
                {
                    float* e = s[2 * ks];
                    float* o = s[2 * ks + 1];
                    float eh0 = __bfloat162float(__float2bfloat16(e[0]));
                    float eh1 = __bfloat162float(__float2bfloat16(e[1]));
                    float eh2 = __bfloat162float(__float2bfloat16(e[2]));
                    float eh3 = __bfloat162float(__float2bfloat16(e[3]));
                    float oh0 = __bfloat162float(__float2bfloat16(o[0]));
                    float oh1 = __bfloat162float(__float2bfloat16(o[1]));
                    float oh2 = __bfloat162float(__float2bfloat16(o[2]));
                    float oh3 = __bfloat162float(__float2bfloat16(o[3]));
                    ph[0] = packbf2(eh0, eh1); ph[1] = packbf2(eh2, eh3);
                    ph[2] = packbf2(oh0, oh1); ph[3] = packbf2(oh2, oh3);
                    pl[0] = packbf2(e[0] - eh0, e[1] - eh1);
                    pl[1] = packbf2(e[2] - eh2, e[3] - eh3);
                    pl[2] = packbf2(o[0] - oh0, o[1] - oh1);
                    pl[3] = packbf2(o[2] - oh2, o[3] - oh3);
                }
                int keyr = ks * 16 + tkey;
#pragma unroll
                for (int np = 0; np < 4; np++) {
                    int nch = np * 2 + tnc;
                    uint32_t vh[4], vl[4];
                    ldsm4t(vh, sV  + keyr * 128 + ((nch ^ (keyr & 7)) * 16));
                    ldsm4t(vl, sVl + keyr * 128 + ((nch ^ (keyr & 7)) * 16));
                    uint32_t bh0[2] = {vh[0], vh[1]}, bh1[2] = {vh[2], vh[3]};
                    uint32_t bl0[2] = {vl[0], vl[1]}, bl1[2] = {vl[2], vl[3]};
                    mma16816(yacc[2 * np],     ph, bh0);
                    mma16816(yacc[2 * np],     ph, bl0);
                    mma16816(yacc[2 * np],     pl, bh0);
                    mma16816(yacc[2 * np + 1], ph, bh1);
                    mma16816(yacc[2 * np + 1], ph, bl1);
                    mma16816(yacc[2 * np + 1], pl, bh1);
                }
            }
        }
        __syncthreads();
    }

    // ---- finalize ----
    l0 += __shfl_xor_sync(0xffffffffu, l0, 1);
    l0 += __shfl_xor_sync(0xffffffffu, l0, 2);
    l1 += __shfl_xor_sync(0xffffffffu, l1, 1);
    l1 += __shfl_xor_sync(0xffffffffu, l1, 2);
    float inv0 = 1.f / l0, inv1 = 1.f / l1;

    int tok0 = b * S_ + qt * 128 + warp * 16 + (lane >> 2);
    int tok1 = tok0 + 8;
#pragma unroll
    for (int nf = 0; nf < 8; nf++) {
        int col = h * 64 + nf * 8 + (lane & 3) * 2;
        float y0 = yacc[nf][0] * inv0, y1 = yacc[nf][1] * inv0;
        float y2 = yacc[nf][2] * inv1, y3 = yacc[nf][3] * inv1;
        float h0 = __bfloat162float(__float2bfloat16(y0));
        float h1 = __bfloat162float(__float2bfloat16(y1));
        float h2 = __bfloat162float(__float2bfloat16(y2));
        float h3 = __bfloat162float(__float2bfloat16(y3));
        *(uint32_t*)(g_yh + (size_t)tok0 * E_ + col) = packbf2(h0, h1);
        *(uint32_t*)(g_yl + (size_t)tok0 * E_ + col) = packbf2(y0 - h0, y1 - h1);
        *(uint32_t*)(g_yh + (size_t)tok1 * E_ + col) = packbf2(h2, h3);
        *(uint32_t*)(g_yl + (size_t)tok1 * E_ + col) = packbf2(y2 - h2, y3 - h3);
    }
}

// ---------------------------------------------------------------------------
// launch — inputs: 0:x 1:ve 2:cos 3:sin 4:attn_mask 5:Wq 6:Wk 7:Wv 8:Wproj 9:Wgate
// ---------------------------------------------------------------------------
extern "C" void kernel_launch(void* const* d_in, const int* in_sizes, int n_in,
                              void* d_out, int out_size)
{
    (void)in_sizes; (void)n_in; (void)out_size;
    const float* x     = (const float*)d_in[0];
    const float* ve    = (const float*)d_in[1];
    const float* cosb  = (const float*)d_in[2];
    const float* sinb  = (const float*)d_in[3];
    const float* Wq    = (const float*)d_in[5];
    const float* Wk    = (const float*)d_in[6];
    const float* Wv    = (const float*)d_in[7];
    const float* Wproj = (const float*)d_in[8];
    const float* Wgate = (const float*)d_in[9];
    float* out = (float*)d_out;

    float* qkv;
    cudaGetSymbolAddress((void**)&qkv, g_qkv);
    __nv_bfloat16 *xh, *xl, *yh, *yl, *wh, *wl;
    cudaGetSymbolAddress((void**)&xh, g_xh);
    cudaGetSymbolAddress((void**)&xl, g_xl);
    cudaGetSymbolAddress((void**)&yh, g_yh);
    cudaGetSymbolAddress((void**)&yl, g_yl);
    cudaGetSymbolAddress((void**)&wh, g_wh);
    cudaGetSymbolAddress((void**)&wl, g_wl);

    static int smem_set = 0;
    if (!smem_set) {
        cudaFuncSetAttribute(attn_mma_kernel,
                             cudaFuncAttributeMaxDynamicSharedMemorySize, ATT_SMEM);
        cudaFuncSetAttribute(gemm_split_pipe,
                             cudaFuncAttributeMaxDynamicSharedMemorySize, GEMM_SMEM);
        smem_set = 1;
    }

    // splits (2 launches)
    {
        int n4 = TOKENS * E_ / 4;
        split_kernel<<<(n4 + 255) / 256, 256>>>(x, xh, xl, n4);
        int w4 = 2560 * E_ / 4;
        splitw_kernel<<<(w4 + 255) / 256, 256>>>(Wq, Wk, Wv, Wproj);
    }

    // fused QKV projection
    {
        dim3 g(1536 / 128, TOKENS / 128);
        gemm_split_pipe<<<g, 256, GEMM_SMEM>>>(xh, xl, wh, wl, qkv,
                                               TOKENS, 1536, E_);
    }

    // gate + ve, rope + rmsnorm (emits bf16 hi/lo q,k,v)
    ew_kernel<<<TOKENS, 256>>>(x, ve, cosb, sinb, Wgate);

    // tensor-core flash attention (emits bf16 hi/lo y)
    {
        dim3 ga(S_ / 128, B_ * NH_);
        attn_mma_kernel<<<ga, 256, ATT_SMEM>>>();
    }

    // output projection
    {
        dim3 gp(E_ / 128, TOKENS / 128);
        gemm_split_pipe<<<gp, 256, GEMM_SMEM>>>(yh, yl, wh + WP_OFF, wl + WP_OFF,
                                                out, TOKENS, E_, E_);
    }
}